// round 2
// baseline (speedup 1.0000x reference)
#include <cuda_runtime.h>
#include <math.h>

// Problem dims (fixed by the dataset)
#define NN 4096   // nodes
#define NE 8192   // edges
#define NGR 256   // graphs
#define AF 9      // atom features
#define BF 4      // bond features
#define H  128    // hidden
#define NL 3      // layers

// ---------------- scratch (static device globals; no allocation) ----------------
__device__ float g_h[NN * H];                    // 2 MB   node features
__device__ float g_eh[NE * H];                   // 4 MB   edge-net hidden
__device__ float g_U[(size_t)NN * H * H];        // 268 MB U[n,j,o] = sum_i h[n,i] W2[j,i,o]
__device__ float g_nbias[NN * H];                // 2 MB   nbias[n,o] = sum_i h[n,i] B2[i,o]
__device__ float g_agg[NN * H];                  // 2 MB   scatter accumulator
__device__ float g_deg[NN];
__device__ float g_mol[NGR * H];
__device__ float g_cnt[NGR];

__device__ __forceinline__ float gelu_exact(float x) {
    return 0.5f * x * (1.0f + erff(x * 0.70710678118654752440f));
}

// ---------------- tiny kernels ----------------
__global__ void k_zero_misc() {
    int i = blockIdx.x * blockDim.x + threadIdx.x;
    if (i < NN) g_deg[i] = 0.f;
    if (i < NGR * H) g_mol[i] = 0.f;
    if (i < NGR) g_cnt[i] = 0.f;
}

__global__ void k_zero_agg() {
    int i = blockIdx.x * blockDim.x + threadIdx.x;
    if (i < NN * H) g_agg[i] = 0.f;
}

__global__ void k_deg(const int* __restrict__ ei) {
    int e = blockIdx.x * blockDim.x + threadIdx.x;
    if (e < NE) atomicAdd(&g_deg[ei[NE + e]], 1.0f);
}

// h = relu(x @ atom_w + atom_b)
__global__ void k_atom(const float* __restrict__ x, const float* __restrict__ w,
                       const float* __restrict__ b) {
    int n = blockIdx.x, o = threadIdx.x;
    __shared__ float xs[AF];
    if (o < AF) xs[o] = x[n * AF + o];
    __syncthreads();
    float acc = b[o];
#pragma unroll
    for (int f = 0; f < AF; f++) acc += xs[f] * w[f * H + o];
    g_h[n * H + o] = fmaxf(acc, 0.f);
}

// eh = gelu(edge_attr @ e1_w[l] + e1_b[l])
__global__ void k_edge(const float* __restrict__ ea, const float* __restrict__ w1,
                       const float* __restrict__ b1) {
    int e = blockIdx.x, o = threadIdx.x;
    __shared__ float es[BF];
    if (o < BF) es[o] = ea[e * BF + o];
    __syncthreads();
    float a = b1[o];
#pragma unroll
    for (int f = 0; f < BF; f++) a += es[f] * w1[f * H + o];
    g_eh[e * H + o] = gelu_exact(a);
}

// U[n,j,:] = h[n,:] @ W2[j]   (64-node x 128-col tile, K=128, 8x8 per-thread microtile)
// blockIdx.y == H  computes nbias[n,:] = h[n,:] @ B2 instead.
__global__ __launch_bounds__(128) void k_U(const float* __restrict__ Bw,
                                           const float* __restrict__ Bb) {
    const int nb = blockIdx.x * 64;
    const int j  = blockIdx.y;
    const float* B = (j < H) ? (Bw + (size_t)j * H * H) : Bb;

    __shared__ float As[16][65];   // [k][row], padded (stride 65 -> conflict-free)
    __shared__ float Bs[16][H];    // [k][o]

    const int tid = threadIdx.x;
    const int tx = tid & 15;       // 16 col-groups of 8
    const int ty = tid >> 4;       // 8 row-groups of 8

    float acc[8][8];
#pragma unroll
    for (int r = 0; r < 8; r++)
#pragma unroll
        for (int c = 0; c < 8; c++) acc[r][c] = 0.f;

    for (int kk = 0; kk < H; kk += 16) {
#pragma unroll
        for (int u = 0; u < 8; u++) {          // A tile: 64x16
            int idx = tid + u * 128;
            int row = idx >> 4, k = idx & 15;
            As[k][row] = g_h[(nb + row) * H + kk + k];
        }
#pragma unroll
        for (int u = 0; u < 16; u++) {         // B tile: 16x128
            int idx = tid + u * 128;
            int k = idx >> 7, o = idx & 127;
            Bs[k][o] = B[(kk + k) * H + o];
        }
        __syncthreads();
#pragma unroll
        for (int k = 0; k < 16; k++) {
            float a[8], b[8];
#pragma unroll
            for (int r = 0; r < 8; r++) a[r] = As[k][ty * 8 + r];
#pragma unroll
            for (int c = 0; c < 8; c++) b[c] = Bs[k][tx * 8 + c];
#pragma unroll
            for (int r = 0; r < 8; r++)
#pragma unroll
                for (int c = 0; c < 8; c++) acc[r][c] += a[r] * b[c];
        }
        __syncthreads();
    }

    if (j < H) {
#pragma unroll
        for (int r = 0; r < 8; r++) {
            int n = nb + ty * 8 + r;
            float* out = g_U + (size_t)n * H * H + j * H + tx * 8;
#pragma unroll
            for (int c = 0; c < 8; c++) out[c] = acc[r][c];
        }
    } else {
#pragma unroll
        for (int r = 0; r < 8; r++) {
            int n = nb + ty * 8 + r;
#pragma unroll
            for (int c = 0; c < 8; c++) g_nbias[n * H + tx * 8 + c] = acc[r][c];
        }
    }
}

// msg[e,o] = sum_j eh[e,j] * U[src,j,o] + nbias[src,o] ; scatter-add to agg[dst]
__global__ void k_msg(const int* __restrict__ ei) {
    int e = blockIdx.x, o = threadIdx.x;
    int src = ei[e], dst = ei[NE + e];
    __shared__ float es[H];
    es[o] = g_eh[e * H + o];
    __syncthreads();
    const float* __restrict__ Up = g_U + (size_t)src * H * H + o;
    float m0 = 0.f, m1 = 0.f, m2 = 0.f, m3 = 0.f;
#pragma unroll 8
    for (int j = 0; j < H; j += 4) {
        m0 += es[j + 0] * Up[(j + 0) * H];
        m1 += es[j + 1] * Up[(j + 1) * H];
        m2 += es[j + 2] * Up[(j + 2) * H];
        m3 += es[j + 3] * Up[(j + 3) * H];
    }
    float m = (m0 + m1) + (m2 + m3) + g_nbias[src * H + o];
    atomicAdd(&g_agg[dst * H + o], m);
}

// h = LN(h + relu(agg/denom + h@root_w + conv_b))
__global__ void k_update(const float* __restrict__ rootw, const float* __restrict__ convb,
                         const float* __restrict__ lng, const float* __restrict__ lnb) {
    int n = blockIdx.x, o = threadIdx.x;
    __shared__ float hs[H];
    __shared__ float sa[4], sb[4];
    float hval = g_h[n * H + o];
    hs[o] = hval;
    __syncthreads();
    float r = convb[o];
#pragma unroll 8
    for (int i = 0; i < H; i++) r += hs[i] * rootw[i * H + o];
    float denom = fmaxf(g_deg[n], 1.0f);
    float hn = fmaxf(g_agg[n * H + o] / denom + r, 0.f);
    float y = hval + hn;

    // block reduction: sum(y), sum(y*y) over 128 lanes
    float s = y, s2 = y * y;
#pragma unroll
    for (int sh = 16; sh > 0; sh >>= 1) {
        s  += __shfl_xor_sync(0xffffffffu, s, sh);
        s2 += __shfl_xor_sync(0xffffffffu, s2, sh);
    }
    int w = o >> 5;
    if ((o & 31) == 0) { sa[w] = s; sb[w] = s2; }
    __syncthreads();
    float ts = sa[0] + sa[1] + sa[2] + sa[3];
    float ts2 = sb[0] + sb[1] + sb[2] + sb[3];
    float mu = ts * (1.0f / H);
    float var = ts2 * (1.0f / H) - mu * mu;
    float inv = rsqrtf(var + 1e-5f);
    g_h[n * H + o] = (y - mu) * inv * lng[o] + lnb[o];
}

__global__ void k_pool(const int* __restrict__ batch) {
    int n = blockIdx.x, o = threadIdx.x;
    int b = batch[n];
    atomicAdd(&g_mol[b * H + o], g_h[n * H + o]);
    if (o == 0) atomicAdd(&g_cnt[b], 1.0f);
}

__global__ void k_head(const float* __restrict__ w1, const float* __restrict__ b1,
                       const float* __restrict__ w2, const float* __restrict__ b2,
                       float* __restrict__ out) {
    int g = blockIdx.x, t = threadIdx.x;  // 64 threads
    __shared__ float ms[H];
    __shared__ float part[2];
    float inv = 1.0f / fmaxf(g_cnt[g], 1.0f);
    ms[t]      = g_mol[g * H + t] * inv;
    ms[t + 64] = g_mol[g * H + t + 64] * inv;
    __syncthreads();
    float a = b1[t];
#pragma unroll 8
    for (int i = 0; i < H; i++) a += ms[i] * w1[i * 64 + t];
    float v = gelu_exact(a) * w2[t];
#pragma unroll
    for (int sh = 16; sh > 0; sh >>= 1) v += __shfl_xor_sync(0xffffffffu, v, sh);
    if ((t & 31) == 0) part[t >> 5] = v;
    __syncthreads();
    if (t == 0) out[g] = part[0] + part[1] + b2[0];
}

// ---------------- launch ----------------
extern "C" void kernel_launch(void* const* d_in, const int* in_sizes, int n_in,
                              void* d_out, int out_size) {
    const float* x        = (const float*)d_in[0];
    const int*   ei       = (const int*)  d_in[1];   // [2, E] int32
    const float* ea       = (const float*)d_in[2];
    const int*   batch    = (const int*)  d_in[3];
    const float* atom_w   = (const float*)d_in[4];
    const float* atom_b   = (const float*)d_in[5];
    const float* e1_w     = (const float*)d_in[6];
    const float* e1_b     = (const float*)d_in[7];
    const float* e2_w     = (const float*)d_in[8];
    const float* e2_b     = (const float*)d_in[9];
    const float* root_w   = (const float*)d_in[10];
    const float* conv_b   = (const float*)d_in[11];
    const float* ln_g     = (const float*)d_in[12];
    const float* ln_b     = (const float*)d_in[13];
    const float* head_w1  = (const float*)d_in[14];
    const float* head_b1  = (const float*)d_in[15];
    const float* head_w2  = (const float*)d_in[16];
    const float* head_b2  = (const float*)d_in[17];
    float* out = (float*)d_out;

    k_zero_misc<<<(NGR * H + 255) / 256, 256>>>();
    k_deg<<<(NE + 255) / 256, 256>>>(ei);
    k_atom<<<NN, H>>>(x, atom_w, atom_b);

    for (int l = 0; l < NL; l++) {
        k_edge<<<NE, H>>>(ea, e1_w + (size_t)l * BF * H, e1_b + (size_t)l * H);
        k_U<<<dim3(NN / 64, H + 1), 128>>>(e2_w + (size_t)l * H * H * H,
                                           e2_b + (size_t)l * H * H);
        k_zero_agg<<<(NN * H + 255) / 256, 256>>>();
        k_msg<<<NE, H>>>(ei);
        k_update<<<NN, H>>>(root_w + (size_t)l * H * H, conv_b + (size_t)l * H,
                            ln_g + (size_t)l * H, ln_b + (size_t)l * H);
    }

    k_pool<<<NN, H>>>(batch);
    k_head<<<NGR, 64>>>(head_w1, head_b1, head_w2, head_b2, out);
}

// round 4
// speedup vs baseline: 2.0678x; 2.0678x over previous
#include <cuda_runtime.h>
#include <cuda_bf16.h>
#include <math.h>
#include <stdint.h>

// Problem dims (fixed by the dataset)
#define NN 4096   // nodes
#define NE 8192   // edges
#define NGR 256   // graphs
#define AF 9      // atom features
#define BF 4      // bond features
#define H  128    // hidden
#define NL 3      // layers

#define NCOL (H * H)          // 16384 output cols of U
#define KTOT 384              // K with 3-term bf16 split folded in: [hi|hi|lo] x [hi|lo|hi]
#define BM 128
#define BN 128
#define BK 64
#define NCHUNK (KTOT / BK)    // 6

// ---------------- scratch (static device globals; no allocation) ----------------
__device__ float g_h[NN * H];
__device__ float g_eh[NE * H];
__device__ float g_U[(size_t)NN * NCOL];          // 268 MB  U[n, j*H+o]
__device__ float g_nbias[NN * H];
__device__ float g_agg[NN * H];
__device__ float g_deg[NN];
__device__ float g_mol[NGR * H];
__device__ float g_cnt[NGR];
__device__ __align__(16) __nv_bfloat16 g_A2[(size_t)NN * KTOT];     // 3 MB
__device__ __align__(16) __nv_bfloat16 g_B2[(size_t)NCOL * KTOT];   // 12.6 MB

__device__ __forceinline__ float gelu_exact(float x) {
    return 0.5f * x * (1.0f + erff(x * 0.70710678118654752440f));
}
__device__ __forceinline__ uint32_t smem_u32(const void* p) {
    uint32_t a;
    asm("{ .reg .u64 t; cvta.to.shared.u64 t, %1; cvt.u32.u64 %0, t; }" : "=r"(a) : "l"(p));
    return a;
}

// ---------------- tiny kernels ----------------
__global__ void k_zero_misc() {
    int i = blockIdx.x * blockDim.x + threadIdx.x;
    if (i < NN) g_deg[i] = 0.f;
    if (i < NGR * H) g_mol[i] = 0.f;
    if (i < NGR) g_cnt[i] = 0.f;
}
__global__ void k_zero_agg() {
    int i = blockIdx.x * blockDim.x + threadIdx.x;
    if (i < NN * H) g_agg[i] = 0.f;
}
__global__ void k_deg(const int* __restrict__ ei) {
    int e = blockIdx.x * blockDim.x + threadIdx.x;
    if (e < NE) atomicAdd(&g_deg[ei[NE + e]], 1.0f);
}

__global__ void k_atom(const float* __restrict__ x, const float* __restrict__ w,
                       const float* __restrict__ b) {
    int n = blockIdx.x, o = threadIdx.x;
    __shared__ float xs[AF];
    if (o < AF) xs[o] = x[n * AF + o];
    __syncthreads();
    float acc = b[o];
#pragma unroll
    for (int f = 0; f < AF; f++) acc += xs[f] * w[f * H + o];
    g_h[n * H + o] = fmaxf(acc, 0.f);
}

__global__ void k_edge(const float* __restrict__ ea, const float* __restrict__ w1,
                       const float* __restrict__ b1) {
    int e = blockIdx.x, o = threadIdx.x;
    __shared__ float es[BF];
    if (o < BF) es[o] = ea[e * BF + o];
    __syncthreads();
    float a = b1[o];
#pragma unroll
    for (int f = 0; f < BF; f++) a += es[f] * w1[f * H + o];
    g_eh[e * H + o] = gelu_exact(a);
}

// h (fp32) -> A'' row [hi | hi | lo]
__global__ void k_split_h() {
    int i = blockIdx.x * blockDim.x + threadIdx.x;
    if (i < NN * H) {
        int n = i >> 7, c = i & 127;
        float v = g_h[i];
        __nv_bfloat16 hi = __float2bfloat16(v);
        __nv_bfloat16 lo = __float2bfloat16(v - __bfloat162float(hi));
        size_t base = (size_t)n * KTOT;
        g_A2[base + c] = hi;
        g_A2[base + 128 + c] = hi;
        g_A2[base + 256 + c] = lo;
    }
}

// W2[j, i*H+o] -> B'' row (j*H+o) = [hi | lo | hi] over i. One warp per out-row.
__global__ void k_permW(const float* __restrict__ W2) {
    int row = blockIdx.x * 4 + (threadIdx.x >> 5);
    int lid = threadIdx.x & 31;
    int j = row >> 7, o = row & 127;
    const float* src = W2 + (size_t)j * NCOL + o;
    size_t base = (size_t)row * KTOT;
#pragma unroll
    for (int t = 0; t < 4; t++) {
        int i = t * 32 + lid;
        float v = src[(size_t)i * H];
        __nv_bfloat16 hi = __float2bfloat16(v);
        __nv_bfloat16 lo = __float2bfloat16(v - __bfloat162float(hi));
        g_B2[base + i] = hi;
        g_B2[base + 128 + i] = lo;
        g_B2[base + 256 + i] = hi;
    }
}

// nbias[n,o] = sum_i h[n,i] * B2bias[i*H+o]   (16 nodes per block)
__global__ __launch_bounds__(128) void k_nbias(const float* __restrict__ Bb) {
    int nb = blockIdx.x * 16, o = threadIdx.x;
    __shared__ float hs[16][H];
    for (int t = o; t < 16 * H; t += 128) hs[t >> 7][t & 127] = g_h[(nb + (t >> 7)) * H + (t & 127)];
    __syncthreads();
    float acc[16];
#pragma unroll
    for (int nn = 0; nn < 16; nn++) acc[nn] = 0.f;
    for (int i = 0; i < H; i++) {
        float b = Bb[i * H + o];
#pragma unroll
        for (int nn = 0; nn < 16; nn++) acc[nn] += hs[nn][i] * b;
    }
#pragma unroll
    for (int nn = 0; nn < 16; nn++) g_nbias[(nb + nn) * H + o] = acc[nn];
}

// ---------------- HMMA GEMM: U = A''[4096,384] @ B''[16384,384]^T ----------------
// CTA 128x128, 8 warps (2x4), warp 64x32. BK=64 double-buffered cp.async, SW128 swizzle.
#define SW(row, kb) (((row) * 128 + (kb)) ^ (((row) & 7) << 4))

__global__ __launch_bounds__(256, 2) void k_U_mma() {
    extern __shared__ char smem[];
    const int tid = threadIdx.x;
    const int warp = tid >> 5, lane = tid & 31;
    const int wm = warp >> 2, wn = warp & 3;
    const int m0 = blockIdx.x * BM;
    const int n0 = blockIdx.y * BN;

    const uint32_t sA = smem_u32(smem);            // 2 x 16KB
    const uint32_t sB = sA + 32768;                // 2 x 16KB

    float c[4][4][4];
#pragma unroll
    for (int mt = 0; mt < 4; mt++)
#pragma unroll
        for (int nt = 0; nt < 4; nt++)
#pragma unroll
            for (int k = 0; k < 4; k++) c[mt][nt][k] = 0.f;

    const char* gA = (const char*)(g_A2 + (size_t)m0 * KTOT);
    const char* gB = (const char*)(g_B2 + (size_t)n0 * KTOT);

#define LOAD_CHUNK(ck, buf)                                                          \
    {                                                                                \
        _Pragma("unroll")                                                            \
        for (int i = 0; i < 4; i++) {                                                \
            int cidx = tid + i * 256;                                                \
            int row = cidx >> 3, kc = cidx & 7;                                      \
            uint32_t sw = SW(row, kc * 16);                                          \
            const void* srcA = gA + (size_t)row * (KTOT * 2) + (ck) * (BK * 2) + kc * 16; \
            const void* srcB = gB + (size_t)row * (KTOT * 2) + (ck) * (BK * 2) + kc * 16; \
            asm volatile("cp.async.cg.shared.global [%0], [%1], 16;" ::              \
                         "r"(sA + (buf) * 16384 + sw), "l"(srcA));                   \
            asm volatile("cp.async.cg.shared.global [%0], [%1], 16;" ::              \
                         "r"(sB + (buf) * 16384 + sw), "l"(srcB));                   \
        }                                                                            \
        asm volatile("cp.async.commit_group;");                                      \
    }

    LOAD_CHUNK(0, 0);

    for (int ck = 0; ck < NCHUNK; ck++) {
        const int buf = ck & 1;
        if (ck + 1 < NCHUNK) {
            LOAD_CHUNK(ck + 1, buf ^ 1);
            asm volatile("cp.async.wait_group 1;");
        } else {
            asm volatile("cp.async.wait_group 0;");
        }
        __syncthreads();

#pragma unroll
        for (int ks = 0; ks < 4; ks++) {
            uint32_t a[4][4];
#pragma unroll
            for (int mt = 0; mt < 4; mt++) {
                int row = wm * 64 + mt * 16 + (lane & 15);
                int kb = ks * 32 + (lane >> 4) * 16;
                uint32_t addr = sA + buf * 16384 + SW(row, kb);
                asm volatile("ldmatrix.sync.aligned.m8n8.x4.shared.b16 {%0,%1,%2,%3}, [%4];"
                             : "=r"(a[mt][0]), "=r"(a[mt][1]), "=r"(a[mt][2]), "=r"(a[mt][3])
                             : "r"(addr));
            }
            uint32_t b[2][4];
#pragma unroll
            for (int bt = 0; bt < 2; bt++) {
                int nrow = wn * 32 + bt * 16 + (lane & 7) + ((lane >> 4) & 1) * 8;
                int kb = ks * 32 + ((lane >> 3) & 1) * 16;
                uint32_t addr = sB + buf * 16384 + SW(nrow, kb);
                asm volatile("ldmatrix.sync.aligned.m8n8.x4.shared.b16 {%0,%1,%2,%3}, [%4];"
                             : "=r"(b[bt][0]), "=r"(b[bt][1]), "=r"(b[bt][2]), "=r"(b[bt][3])
                             : "r"(addr));
            }
#pragma unroll
            for (int mt = 0; mt < 4; mt++) {
#pragma unroll
                for (int nt = 0; nt < 4; nt++) {
                    uint32_t b0 = b[nt >> 1][(nt & 1) * 2];
                    uint32_t b1 = b[nt >> 1][(nt & 1) * 2 + 1];
                    asm volatile(
                        "mma.sync.aligned.m16n8k16.row.col.f32.bf16.bf16.f32 "
                        "{%0,%1,%2,%3}, {%4,%5,%6,%7}, {%8,%9}, {%0,%1,%2,%3};"
                        : "+f"(c[mt][nt][0]), "+f"(c[mt][nt][1]),
                          "+f"(c[mt][nt][2]), "+f"(c[mt][nt][3])
                        : "r"(a[mt][0]), "r"(a[mt][1]), "r"(a[mt][2]), "r"(a[mt][3]),
                          "r"(b0), "r"(b1));
                }
            }
        }
        __syncthreads();
    }

    // epilogue: direct float2 stores
#pragma unroll
    for (int mt = 0; mt < 4; mt++) {
        int r0 = m0 + wm * 64 + mt * 16 + (lane >> 2);
#pragma unroll
        for (int nt = 0; nt < 4; nt++) {
            int col = n0 + wn * 32 + nt * 8 + (lane & 3) * 2;
            *(float2*)(g_U + (size_t)r0 * NCOL + col) = make_float2(c[mt][nt][0], c[mt][nt][1]);
            *(float2*)(g_U + (size_t)(r0 + 8) * NCOL + col) = make_float2(c[mt][nt][2], c[mt][nt][3]);
        }
    }
}
#define GEMM_SMEM 65536

// msg[e,o] = sum_j eh[e,j] * U[src,j,o] + nbias[src,o] ; scatter-add to agg[dst]
__global__ void k_msg(const int* __restrict__ ei) {
    int e = blockIdx.x, o = threadIdx.x;
    int src = ei[e], dst = ei[NE + e];
    __shared__ float es[H];
    es[o] = g_eh[e * H + o];
    __syncthreads();
    const float* __restrict__ Up = g_U + (size_t)src * NCOL + o;
    float m0 = 0.f, m1 = 0.f, m2 = 0.f, m3 = 0.f;
#pragma unroll 8
    for (int j = 0; j < H; j += 4) {
        m0 += es[j + 0] * Up[(j + 0) * H];
        m1 += es[j + 1] * Up[(j + 1) * H];
        m2 += es[j + 2] * Up[(j + 2) * H];
        m3 += es[j + 3] * Up[(j + 3) * H];
    }
    float m = (m0 + m1) + (m2 + m3) + g_nbias[src * H + o];
    atomicAdd(&g_agg[dst * H + o], m);
}

// h = LN(h + relu(agg/denom + h@root_w + conv_b))
__global__ void k_update(const float* __restrict__ rootw, const float* __restrict__ convb,
                         const float* __restrict__ lng, const float* __restrict__ lnb) {
    int n = blockIdx.x, o = threadIdx.x;
    __shared__ float hs[H];
    __shared__ float sa[4], sb2[4];
    float hval = g_h[n * H + o];
    hs[o] = hval;
    __syncthreads();
    float r = convb[o];
#pragma unroll 8
    for (int i = 0; i < H; i++) r += hs[i] * rootw[i * H + o];
    float denom = fmaxf(g_deg[n], 1.0f);
    float hn = fmaxf(g_agg[n * H + o] / denom + r, 0.f);
    float y = hval + hn;

    float s = y, s2 = y * y;
#pragma unroll
    for (int sh = 16; sh > 0; sh >>= 1) {
        s  += __shfl_xor_sync(0xffffffffu, s, sh);
        s2 += __shfl_xor_sync(0xffffffffu, s2, sh);
    }
    int w = o >> 5;
    if ((o & 31) == 0) { sa[w] = s; sb2[w] = s2; }
    __syncthreads();
    float ts = sa[0] + sa[1] + sa[2] + sa[3];
    float ts2 = sb2[0] + sb2[1] + sb2[2] + sb2[3];
    float mu = ts * (1.0f / H);
    float var = ts2 * (1.0f / H) - mu * mu;
    float inv = rsqrtf(var + 1e-5f);
    g_h[n * H + o] = (y - mu) * inv * lng[o] + lnb[o];
}

__global__ void k_pool(const int* __restrict__ batch) {
    int n = blockIdx.x, o = threadIdx.x;
    int b = batch[n];
    atomicAdd(&g_mol[b * H + o], g_h[n * H + o]);
    if (o == 0) atomicAdd(&g_cnt[b], 1.0f);
}

__global__ void k_head(const float* __restrict__ w1, const float* __restrict__ b1,
                       const float* __restrict__ w2, const float* __restrict__ b2,
                       float* __restrict__ out) {
    int g = blockIdx.x, t = threadIdx.x;  // 64 threads
    __shared__ float ms[H];
    __shared__ float part[2];
    float inv = 1.0f / fmaxf(g_cnt[g], 1.0f);
    ms[t]      = g_mol[g * H + t] * inv;
    ms[t + 64] = g_mol[g * H + t + 64] * inv;
    __syncthreads();
    float a = b1[t];
#pragma unroll 8
    for (int i = 0; i < H; i++) a += ms[i] * w1[i * 64 + t];
    float v = gelu_exact(a) * w2[t];
#pragma unroll
    for (int sh = 16; sh > 0; sh >>= 1) v += __shfl_xor_sync(0xffffffffu, v, sh);
    if ((t & 31) == 0) part[t >> 5] = v;
    __syncthreads();
    if (t == 0) out[g] = part[0] + part[1] + b2[0];
}

// ---------------- launch ----------------
extern "C" void kernel_launch(void* const* d_in, const int* in_sizes, int n_in,
                              void* d_out, int out_size) {
    const float* x        = (const float*)d_in[0];
    const int*   ei       = (const int*)  d_in[1];
    const float* ea       = (const float*)d_in[2];
    const int*   batch    = (const int*)  d_in[3];
    const float* atom_w   = (const float*)d_in[4];
    const float* atom_b   = (const float*)d_in[5];
    const float* e1_w     = (const float*)d_in[6];
    const float* e1_b     = (const float*)d_in[7];
    const float* e2_w     = (const float*)d_in[8];
    const float* e2_b     = (const float*)d_in[9];
    const float* root_w   = (const float*)d_in[10];
    const float* conv_b   = (const float*)d_in[11];
    const float* ln_g     = (const float*)d_in[12];
    const float* ln_b     = (const float*)d_in[13];
    const float* head_w1  = (const float*)d_in[14];
    const float* head_b1  = (const float*)d_in[15];
    const float* head_w2  = (const float*)d_in[16];
    const float* head_b2  = (const float*)d_in[17];
    float* out = (float*)d_out;

    cudaFuncSetAttribute(k_U_mma, cudaFuncAttributeMaxDynamicSharedMemorySize, GEMM_SMEM);

    k_zero_misc<<<(NGR * H + 255) / 256, 256>>>();
    k_deg<<<(NE + 255) / 256, 256>>>(ei);
    k_atom<<<NN, H>>>(x, atom_w, atom_b);

    for (int l = 0; l < NL; l++) {
        k_edge<<<NE, H>>>(ea, e1_w + (size_t)l * BF * H, e1_b + (size_t)l * H);
        k_permW<<<NCOL / 4, 128>>>(e2_w + (size_t)l * H * NCOL);
        k_split_h<<<(NN * H + 255) / 256, 256>>>();
        k_nbias<<<NN / 16, 128>>>(e2_b + (size_t)l * NCOL);
        k_zero_agg<<<(NN * H + 255) / 256, 256>>>();
        k_U_mma<<<dim3(NN / BM, NCOL / BN), 256, GEMM_SMEM>>>();
        k_msg<<<NE, H>>>(ei);
        k_update<<<NN, H>>>(root_w + (size_t)l * H * H, conv_b + (size_t)l * H,
                            ln_g + (size_t)l * H, ln_b + (size_t)l * H);
    }

    k_pool<<<NN, H>>>(batch);
    k_head<<<NGR, 64>>>(head_w1, head_b1, head_w2, head_b2, out);
}

// round 5
// speedup vs baseline: 2.6379x; 1.2757x over previous
#include <cuda_runtime.h>
#include <cuda_bf16.h>
#include <cuda_fp16.h>
#include <math.h>
#include <stdint.h>

#define NN 4096
#define NE 8192
#define NGR 256
#define AF 9
#define BF 4
#define H  128
#define NL 3

#define NCOL (H * H)          // 16384
#define KTOT 384              // [hi|hi|lo] x [hi|lo|hi] 3-term bf16 split
#define BM 128
#define BN 128
#define BK 64
#define NCHUNK (KTOT / BK)
#define NBROWS (NCOL + H)     // B'' rows incl. bias rows

// ---------------- scratch ----------------
__device__ float g_h[NN * H];
__device__ float g_eh[NE * H];
__device__ __half g_U[(size_t)NN * NCOL];         // 134 MB, fp16
__device__ float g_nbias[NN * H];
__device__ float g_agg[NN * H];
__device__ float g_deg[NN];
__device__ float g_mol[NGR * H];
__device__ float g_cnt[NGR];
__device__ __align__(16) __nv_bfloat16 g_A2[(size_t)NN * KTOT];
__device__ __align__(16) __nv_bfloat16 g_B2[(size_t)NBROWS * KTOT];
__device__ int g_hist[NN];
__device__ int g_base[NN];
__device__ int g_cnt2[NN];
__device__ int g_perm[NE];

__device__ __forceinline__ float gelu_exact(float x) {
    return 0.5f * x * (1.0f + erff(x * 0.70710678118654752440f));
}
__device__ __forceinline__ uint32_t smem_u32(const void* p) {
    uint32_t a;
    asm("{ .reg .u64 t; cvta.to.shared.u64 t, %1; cvt.u32.u64 %0, t; }" : "=r"(a) : "l"(p));
    return a;
}

// ---------------- small kernels ----------------
__global__ void k_zero() {   // zero agg + deg + mol + cnt + hist + cnt2
    int i = blockIdx.x * blockDim.x + threadIdx.x;
    if (i < NN * H) g_agg[i] = 0.f;
    if (i < NN) { g_deg[i] = 0.f; g_hist[i] = 0; g_cnt2[i] = 0; }
    if (i < NGR * H) g_mol[i] = 0.f;
    if (i < NGR) g_cnt[i] = 0.f;
}
__global__ void k_zero_agg() {
    int i = blockIdx.x * blockDim.x + threadIdx.x;
    if (i < NN * H) g_agg[i] = 0.f;
}
__global__ void k_deghist(const int* __restrict__ ei) {
    int e = blockIdx.x * blockDim.x + threadIdx.x;
    if (e < NE) {
        atomicAdd(&g_deg[ei[NE + e]], 1.0f);
        atomicAdd(&g_hist[ei[e]], 1);
    }
}
// exclusive scan of hist -> base (one block, 128 threads x 32 elems)
__global__ void k_scan() {
    __shared__ int ws[128];
    int t = threadIdx.x;
    int s = 0;
#pragma unroll
    for (int i = 0; i < 32; i++) s += g_hist[t * 32 + i];
    ws[t] = s;
    __syncthreads();
    if (t == 0) {
        int acc = 0;
        for (int i = 0; i < 128; i++) { int v = ws[i]; ws[i] = acc; acc += v; }
    }
    __syncthreads();
    int start = ws[t];
    s = 0;
#pragma unroll
    for (int i = 0; i < 32; i++) {
        g_base[t * 32 + i] = start + s;
        s += g_hist[t * 32 + i];
    }
}
__global__ void k_scatter(const int* __restrict__ ei) {
    int e = blockIdx.x * blockDim.x + threadIdx.x;
    if (e < NE) {
        int src = ei[e];
        int pos = g_base[src] + atomicAdd(&g_cnt2[src], 1);
        g_perm[pos] = e;
    }
}

__global__ void k_atom(const float* __restrict__ x, const float* __restrict__ w,
                       const float* __restrict__ b) {
    int n = blockIdx.x, o = threadIdx.x;
    __shared__ float xs[AF];
    if (o < AF) xs[o] = x[n * AF + o];
    __syncthreads();
    float acc = b[o];
#pragma unroll
    for (int f = 0; f < AF; f++) acc += xs[f] * w[f * H + o];
    g_h[n * H + o] = fmaxf(acc, 0.f);
}

__global__ void k_edge(const float* __restrict__ ea, const float* __restrict__ w1,
                       const float* __restrict__ b1) {
    int e = blockIdx.x, o = threadIdx.x;
    __shared__ float es[BF];
    if (o < BF) es[o] = ea[e * BF + o];
    __syncthreads();
    float a = b1[o];
#pragma unroll
    for (int f = 0; f < BF; f++) a += es[f] * w1[f * H + o];
    g_eh[e * H + o] = gelu_exact(a);
}

// h -> A'' row [hi | hi | lo]
__global__ void k_split_h() {
    int i = blockIdx.x * blockDim.x + threadIdx.x;
    if (i < NN * H) {
        int n = i >> 7, c = i & 127;
        float v = g_h[i];
        __nv_bfloat16 hi = __float2bfloat16(v);
        __nv_bfloat16 lo = __float2bfloat16(v - __bfloat162float(hi));
        size_t base = (size_t)n * KTOT;
        g_A2[base + c] = hi;
        g_A2[base + 128 + c] = hi;
        g_A2[base + 256 + c] = lo;
    }
}

// W2[j, i*H+o] -> B'' row (j*H+o) = [hi | lo | hi] over i
__global__ void k_permW(const float* __restrict__ W2) {
    int row = blockIdx.x * 4 + (threadIdx.x >> 5);
    int lid = threadIdx.x & 31;
    int j = row >> 7, o = row & 127;
    const float* src = W2 + (size_t)j * NCOL + o;
    size_t base = (size_t)row * KTOT;
#pragma unroll
    for (int t = 0; t < 4; t++) {
        int i = t * 32 + lid;
        float v = src[(size_t)i * H];
        __nv_bfloat16 hi = __float2bfloat16(v);
        __nv_bfloat16 lo = __float2bfloat16(v - __bfloat162float(hi));
        g_B2[base + i] = hi;
        g_B2[base + 128 + i] = lo;
        g_B2[base + 256 + i] = hi;
    }
}
// bias rows: B'' row (NCOL+o) over i from e2_b-as-matrix? No: e2_b is [H*H] -> treated as
// bias matrix Bb[i_out? ] ... nbias[n,o] = sum_i h[n,i] * Bb_mat[i][o] where Bb_mat = e2_b
// reshaped [H,H]?  NO: e2_b is a bias over the H*H outputs of the second edge-net layer:
// (eh @ e2_w + e2_b) -> w[e,(j,o)].  msg = sum_j eh? ... bias contribution to msg:
// sum_{j,i} eh?  Careful: w[e,j,o] = sum_m eh[e,m] e2_w[m,(j,o)] + e2_b[(j,o)].
// msg[e,o] = sum_i h[src,i] w[e,i,o]  (einsum 'ei,eio->eo', so the CONTRACTED index of w
// is its middle dim). With w rows indexed (i,o): msg = sum_i h[src,i]*(sum_m eh e2_w[m,(i,o)])
//  + sum_i h[src,i]*e2_b[(i,o)].  So bias term nbias[n,o] = sum_i h[n,i]*e2_b[i*H+o].  ✓
__global__ void k_permB(const float* __restrict__ Bb) {
    int o = blockIdx.x * 4 + (threadIdx.x >> 5);
    int lid = threadIdx.x & 31;
    size_t base = (size_t)(NCOL + o) * KTOT;
#pragma unroll
    for (int t = 0; t < 4; t++) {
        int i = t * 32 + lid;
        float v = Bb[(size_t)i * H + o];
        __nv_bfloat16 hi = __float2bfloat16(v);
        __nv_bfloat16 lo = __float2bfloat16(v - __bfloat162float(hi));
        g_B2[base + i] = hi;
        g_B2[base + 128 + i] = lo;
        g_B2[base + 256 + i] = hi;
    }
}

// ---------------- HMMA GEMM ----------------
#define SW(row, kb) (((row) * 128 + (kb)) ^ (((row) & 7) << 4))

__global__ __launch_bounds__(256, 2) void k_U_mma() {
    extern __shared__ char smem[];
    const int tid = threadIdx.x;
    const int warp = tid >> 5, lane = tid & 31;
    const int wm = warp >> 2, wn = warp & 3;
    const int m0 = blockIdx.x * BM;
    const int n0 = blockIdx.y * BN;

    const uint32_t sA = smem_u32(smem);
    const uint32_t sB = sA + 32768;

    float c[4][4][4];
#pragma unroll
    for (int mt = 0; mt < 4; mt++)
#pragma unroll
        for (int nt = 0; nt < 4; nt++)
#pragma unroll
            for (int k = 0; k < 4; k++) c[mt][nt][k] = 0.f;

    const char* gA = (const char*)(g_A2 + (size_t)m0 * KTOT);
    const char* gB = (const char*)(g_B2 + (size_t)n0 * KTOT);

#define LOAD_CHUNK(ck, buf)                                                          \
    {                                                                                \
        _Pragma("unroll")                                                            \
        for (int i = 0; i < 4; i++) {                                                \
            int cidx = tid + i * 256;                                                \
            int row = cidx >> 3, kc = cidx & 7;                                      \
            uint32_t sw = SW(row, kc * 16);                                          \
            const void* srcA = gA + (size_t)row * (KTOT * 2) + (ck) * (BK * 2) + kc * 16; \
            const void* srcB = gB + (size_t)row * (KTOT * 2) + (ck) * (BK * 2) + kc * 16; \
            asm volatile("cp.async.cg.shared.global [%0], [%1], 16;" ::              \
                         "r"(sA + (buf) * 16384 + sw), "l"(srcA));                   \
            asm volatile("cp.async.cg.shared.global [%0], [%1], 16;" ::              \
                         "r"(sB + (buf) * 16384 + sw), "l"(srcB));                   \
        }                                                                            \
        asm volatile("cp.async.commit_group;");                                      \
    }

    LOAD_CHUNK(0, 0);

    for (int ck = 0; ck < NCHUNK; ck++) {
        const int buf = ck & 1;
        if (ck + 1 < NCHUNK) {
            LOAD_CHUNK(ck + 1, buf ^ 1);
            asm volatile("cp.async.wait_group 1;");
        } else {
            asm volatile("cp.async.wait_group 0;");
        }
        __syncthreads();

#pragma unroll
        for (int ks = 0; ks < 4; ks++) {
            uint32_t a[4][4];
#pragma unroll
            for (int mt = 0; mt < 4; mt++) {
                int row = wm * 64 + mt * 16 + (lane & 15);
                int kb = ks * 32 + (lane >> 4) * 16;
                uint32_t addr = sA + buf * 16384 + SW(row, kb);
                asm volatile("ldmatrix.sync.aligned.m8n8.x4.shared.b16 {%0,%1,%2,%3}, [%4];"
                             : "=r"(a[mt][0]), "=r"(a[mt][1]), "=r"(a[mt][2]), "=r"(a[mt][3])
                             : "r"(addr));
            }
            uint32_t b[2][4];
#pragma unroll
            for (int bt = 0; bt < 2; bt++) {
                int nrow = wn * 32 + bt * 16 + (lane & 7) + ((lane >> 4) & 1) * 8;
                int kb = ks * 32 + ((lane >> 3) & 1) * 16;
                uint32_t addr = sB + buf * 16384 + SW(nrow, kb);
                asm volatile("ldmatrix.sync.aligned.m8n8.x4.shared.b16 {%0,%1,%2,%3}, [%4];"
                             : "=r"(b[bt][0]), "=r"(b[bt][1]), "=r"(b[bt][2]), "=r"(b[bt][3])
                             : "r"(addr));
            }
#pragma unroll
            for (int mt = 0; mt < 4; mt++) {
#pragma unroll
                for (int nt = 0; nt < 4; nt++) {
                    uint32_t b0 = b[nt >> 1][(nt & 1) * 2];
                    uint32_t b1 = b[nt >> 1][(nt & 1) * 2 + 1];
                    asm volatile(
                        "mma.sync.aligned.m16n8k16.row.col.f32.bf16.bf16.f32 "
                        "{%0,%1,%2,%3}, {%4,%5,%6,%7}, {%8,%9}, {%0,%1,%2,%3};"
                        : "+f"(c[mt][nt][0]), "+f"(c[mt][nt][1]),
                          "+f"(c[mt][nt][2]), "+f"(c[mt][nt][3])
                        : "r"(a[mt][0]), "r"(a[mt][1]), "r"(a[mt][2]), "r"(a[mt][3]),
                          "r"(b0), "r"(b1));
                }
            }
        }
        __syncthreads();
    }

    // epilogue: fp16 U tiles; last n-tile (bias) -> fp32 g_nbias
    if (blockIdx.y < NCOL / BN) {
#pragma unroll
        for (int mt = 0; mt < 4; mt++) {
            int r0 = m0 + wm * 64 + mt * 16 + (lane >> 2);
#pragma unroll
            for (int nt = 0; nt < 4; nt++) {
                int col = n0 + wn * 32 + nt * 8 + (lane & 3) * 2;
                *(__half2*)(g_U + (size_t)r0 * NCOL + col) =
                    __floats2half2_rn(c[mt][nt][0], c[mt][nt][1]);
                *(__half2*)(g_U + (size_t)(r0 + 8) * NCOL + col) =
                    __floats2half2_rn(c[mt][nt][2], c[mt][nt][3]);
            }
        }
    } else {
#pragma unroll
        for (int mt = 0; mt < 4; mt++) {
            int r0 = m0 + wm * 64 + mt * 16 + (lane >> 2);
#pragma unroll
            for (int nt = 0; nt < 4; nt++) {
                int col = wn * 32 + nt * 8 + (lane & 3) * 2;
                *(float2*)(g_nbias + (size_t)r0 * H + col) = make_float2(c[mt][nt][0], c[mt][nt][1]);
                *(float2*)(g_nbias + (size_t)(r0 + 8) * H + col) = make_float2(c[mt][nt][2], c[mt][nt][3]);
            }
        }
    }
}
#define GEMM_SMEM 65536

// msg[e,o] = sum_j eh[e,j]*U[src,j,o] + nbias[src,o]; scatter-add. 64 threads, 2 cols each.
__global__ __launch_bounds__(64) void k_msg(const int* __restrict__ ei) {
    int e = g_perm[blockIdx.x];
    int src = ei[e], dst = ei[NE + e];
    int t = threadIdx.x;
    __shared__ float es[H];
    es[t] = g_eh[e * H + t];
    es[t + 64] = g_eh[e * H + 64 + t];
    __syncthreads();
    const __half2* __restrict__ Up = (const __half2*)g_U + (size_t)src * (NCOL / 2) + t;
    float m0 = 0.f, m1 = 0.f;
#pragma unroll 8
    for (int j = 0; j < H; j++) {
        float2 u = __half22float2(Up[j * (H / 2)]);
        m0 += es[j] * u.x;
        m1 += es[j] * u.y;
    }
    const float2 nb = *(const float2*)(g_nbias + (size_t)src * H + 2 * t);
    atomicAdd(&g_agg[dst * H + 2 * t], m0 + nb.x);
    atomicAdd(&g_agg[dst * H + 2 * t + 1], m1 + nb.y);
}

__global__ void k_update(const float* __restrict__ rootw, const float* __restrict__ convb,
                         const float* __restrict__ lng, const float* __restrict__ lnb) {
    int n = blockIdx.x, o = threadIdx.x;
    __shared__ float hs[H];
    __shared__ float sa[4], sb2[4];
    float hval = g_h[n * H + o];
    hs[o] = hval;
    __syncthreads();
    float r = convb[o];
#pragma unroll 8
    for (int i = 0; i < H; i++) r += hs[i] * rootw[i * H + o];
    float denom = fmaxf(g_deg[n], 1.0f);
    float hn = fmaxf(g_agg[n * H + o] / denom + r, 0.f);
    float y = hval + hn;

    float s = y, s2 = y * y;
#pragma unroll
    for (int sh = 16; sh > 0; sh >>= 1) {
        s  += __shfl_xor_sync(0xffffffffu, s, sh);
        s2 += __shfl_xor_sync(0xffffffffu, s2, sh);
    }
    int w = o >> 5;
    if ((o & 31) == 0) { sa[w] = s; sb2[w] = s2; }
    __syncthreads();
    float ts = sa[0] + sa[1] + sa[2] + sa[3];
    float ts2 = sb2[0] + sb2[1] + sb2[2] + sb2[3];
    float mu = ts * (1.0f / H);
    float var = ts2 * (1.0f / H) - mu * mu;
    float inv = rsqrtf(var + 1e-5f);
    g_h[n * H + o] = (y - mu) * inv * lng[o] + lnb[o];
}

__global__ void k_pool(const int* __restrict__ batch) {
    int n = blockIdx.x, o = threadIdx.x;
    int b = batch[n];
    atomicAdd(&g_mol[b * H + o], g_h[n * H + o]);
    if (o == 0) atomicAdd(&g_cnt[b], 1.0f);
}

__global__ void k_head(const float* __restrict__ w1, const float* __restrict__ b1,
                       const float* __restrict__ w2, const float* __restrict__ b2,
                       float* __restrict__ out) {
    int g = blockIdx.x, t = threadIdx.x;
    __shared__ float ms[H];
    __shared__ float part[2];
    float inv = 1.0f / fmaxf(g_cnt[g], 1.0f);
    ms[t]      = g_mol[g * H + t] * inv;
    ms[t + 64] = g_mol[g * H + t + 64] * inv;
    __syncthreads();
    float a = b1[t];
#pragma unroll 8
    for (int i = 0; i < H; i++) a += ms[i] * w1[i * 64 + t];
    float v = gelu_exact(a) * w2[t];
#pragma unroll
    for (int sh = 16; sh > 0; sh >>= 1) v += __shfl_xor_sync(0xffffffffu, v, sh);
    if ((t & 31) == 0) part[t >> 5] = v;
    __syncthreads();
    if (t == 0) out[g] = part[0] + part[1] + b2[0];
}

// ---------------- launch ----------------
extern "C" void kernel_launch(void* const* d_in, const int* in_sizes, int n_in,
                              void* d_out, int out_size) {
    const float* x        = (const float*)d_in[0];
    const int*   ei       = (const int*)  d_in[1];
    const float* ea       = (const float*)d_in[2];
    const int*   batch    = (const int*)  d_in[3];
    const float* atom_w   = (const float*)d_in[4];
    const float* atom_b   = (const float*)d_in[5];
    const float* e1_w     = (const float*)d_in[6];
    const float* e1_b     = (const float*)d_in[7];
    const float* e2_w     = (const float*)d_in[8];
    const float* e2_b     = (const float*)d_in[9];
    const float* root_w   = (const float*)d_in[10];
    const float* conv_b   = (const float*)d_in[11];
    const float* ln_g     = (const float*)d_in[12];
    const float* ln_b     = (const float*)d_in[13];
    const float* head_w1  = (const float*)d_in[14];
    const float* head_b1  = (const float*)d_in[15];
    const float* head_w2  = (const float*)d_in[16];
    const float* head_b2  = (const float*)d_in[17];
    float* out = (float*)d_out;

    cudaFuncSetAttribute(k_U_mma, cudaFuncAttributeMaxDynamicSharedMemorySize, GEMM_SMEM);

    dim3 gemm_grid(NN / BM, NCOL / BN + 1);   // +1 n-tile for nbias

    // Ordered so launch index 5 (ncu -s 5 -c 1) is the layer-0 GEMM.
    k_atom<<<NN, H>>>(x, atom_w, atom_b);                                  // 0
    k_split_h<<<(NN * H + 255) / 256, 256>>>();                            // 1
    k_permW<<<NCOL / 4, 128>>>(e2_w);                                      // 2
    k_permB<<<H / 4, 128>>>(e2_b);                                         // 3
    k_zero<<<(NN * H + 255) / 256, 256>>>();                               // 4
    k_U_mma<<<gemm_grid, 256, GEMM_SMEM>>>();                              // 5  <- profiled
    k_deghist<<<(NE + 255) / 256, 256>>>(ei);                              // 6
    k_scan<<<1, 128>>>();                                                  // 7
    k_scatter<<<(NE + 255) / 256, 256>>>(ei);                              // 8
    k_edge<<<NE, H>>>(ea, e1_w, e1_b);                                     // 9
    k_msg<<<NE, 64>>>(ei);                                                 // 10
    k_update<<<NN, H>>>(root_w, conv_b, ln_g, ln_b);                       // 11

    for (int l = 1; l < NL; l++) {
        k_edge<<<NE, H>>>(ea, e1_w + (size_t)l * BF * H, e1_b + (size_t)l * H);
        k_permW<<<NCOL / 4, 128>>>(e2_w + (size_t)l * H * NCOL);
        k_permB<<<H / 4, 128>>>(e2_b + (size_t)l * NCOL);
        k_split_h<<<(NN * H + 255) / 256, 256>>>();
        k_zero_agg<<<(NN * H + 255) / 256, 256>>>();
        k_U_mma<<<gemm_grid, 256, GEMM_SMEM>>>();
        k_msg<<<NE, 64>>>(ei);
        k_update<<<NN, H>>>(root_w + (size_t)l * H * H, conv_b + (size_t)l * H,
                            ln_g + (size_t)l * H, ln_b + (size_t)l * H);
    }

    k_pool<<<NN, H>>>(batch);
    k_head<<<NGR, 64>>>(head_w1, head_b1, head_w2, head_b2, out);
}